// round 16
// baseline (speedup 1.0000x reference)
#include <cuda_runtime.h>

#define BB 512
#define SS 1024
#define TT 64
#define WARPS_PER_CTA 4
#define CTAS (BB / WARPS_PER_CTA)   // 128

#define LOG2E 1.4426950408889634f
#define LN2   0.6931471805599453f
#define LN64  4.1588830833596715f

// Precomputed shifted transition exponentials (step-invariant).
__device__ float g_E[TT * TT];     // E'[t][k] = exp(trans[t][k] - rowmax[t])
__device__ float g_rmax[TT];       // rowmax[t] = max_k trans[t][k]

// ---------------------------------------------------------------------------
// prep: E' = exp(trans - rowmax) ; one block per row t, 64 threads (2 warps)
// ---------------------------------------------------------------------------
__global__ void crf_prep_kernel(const float* __restrict__ trans) {
    int t = blockIdx.x;
    int k = threadIdx.x;
    float x = trans[t * TT + k];

    __shared__ float sm[2];
    int i = __float_as_int(x);
    i = (i >= 0) ? i : (i ^ 0x7FFFFFFF);
    i = __reduce_max_sync(0xFFFFFFFFu, i);
    float wm = __int_as_float((i >= 0) ? i : (i ^ 0x7FFFFFFF));
    if ((k & 31) == 0) sm[k >> 5] = wm;
    __syncthreads();
    float rmax = fmaxf(sm[0], sm[1]);

    g_E[t * TT + k] = __expf(x - rmax);
    if (k == 0) g_rmax[t] = rmax;
}

// ---------------------------------------------------------------------------
// packed f32x2 helpers (Blackwell packed fp32 pipe; PTX-only)
// ---------------------------------------------------------------------------
typedef unsigned long long u64;

__device__ __forceinline__ u64 pk2(float lo, float hi) {
    u64 r; asm("mov.b64 %0, {%1, %2};" : "=l"(r) : "f"(lo), "f"(hi)); return r;
}
__device__ __forceinline__ void upk2(float& lo, float& hi, u64 v) {
    asm("mov.b64 {%0, %1}, %2;" : "=f"(lo), "=f"(hi) : "l"(v));
}
__device__ __forceinline__ u64 fma2(u64 a, u64 b, u64 c) {
    u64 d; asm("fma.rn.f32x2 %0, %1, %2, %3;" : "=l"(d) : "l"(a), "l"(b), "l"(c));
    return d;
}
__device__ __forceinline__ u64 add2(u64 a, u64 b) {
    u64 d; asm("add.rn.f32x2 %0, %1, %2;" : "=l"(d) : "l"(a), "l"(b));
    return d;
}
__device__ __forceinline__ float ex2(float x) {
    float r; asm("ex2.approx.ftz.f32 %0, %1;" : "=f"(r) : "f"(x)); return r;
}
__device__ __forceinline__ float lg2(float x) {
    float r; asm("lg2.approx.ftz.f32 %0, %1;" : "=f"(r) : "f"(x)); return r;
}

// monotone float<->ordered-int map for REDUX-based float max (general floats)
__device__ __forceinline__ int fmap(float x) {
    int i = __float_as_int(x);
    return (i >= 0) ? i : (i ^ 0x7FFFFFFF);
}
__device__ __forceinline__ float funmap(int i) {
    return __int_as_float((i >= 0) ? i : (i ^ 0x7FFFFFFF));
}

// ---------------------------------------------------------------------------
// main scan: one warp per batch; lane owns ADJACENT states (2l, 2l+1).
//
// Exp-domain chain: P[t] = 2^(A[t] - s) carried directly;
//   P_next = S * G, S = dot(E'[t,:], P), G = 2^(F - s') computed off-chain.
// Shift maintenance is INTEGER-EXPONENT arithmetic (no lg2, no ex2 for H):
//   d  = (exp_field(maxP) - 126) + cmax          (e+1 > log2 maxP, rigorous)
//   sN = sC + (float)d ;  H = 2^(-d) by bit-build
//   cmax = max(0, ceil(maxAbsFeat*log2e + Rp2))  (computed one iter early)
// All off-chain operands are >=1 iteration old. Output path: (F,S) latched
// on masked steps; A = F + lg2(S) once after the loop.
// ---------------------------------------------------------------------------
__global__ void __launch_bounds__(WARPS_PER_CTA * 32, 1) crf_scan_kernel(
    const float* __restrict__ feats,   // [B, S, T]
    const float* __restrict__ masks,   // [B, S]
    float* __restrict__ out)           // [B, T]
{
    const int wid  = threadIdx.x >> 5;
    const int lane = threadIdx.x & 31;
    const int b    = blockIdx.x * WARPS_PER_CTA + wid;
    const int t0 = 2 * lane, t1 = 2 * lane + 1;

    // per-warp double-buffered P exchange (broadcast reads -> conflict-free)
    __shared__ __align__(16) float vbuf[WARPS_PER_CTA][2][TT];

    // E' rows for this lane's two states, packed as f32x2 pairs over k
    u64 e0[32], e1[32];
    {
        const float4* r0p = (const float4*)(g_E + t0 * TT);
        const float4* r1p = (const float4*)(g_E + t1 * TT);
#pragma unroll
        for (int j = 0; j < 16; j++) {
            float4 a = r0p[j];
            e0[2 * j]     = pk2(a.x, a.y);
            e0[2 * j + 1] = pk2(a.z, a.w);
            float4 c = r1p[j];
            e1[2 * j]     = pk2(c.x, c.y);
            e1[2 * j + 1] = pk2(c.z, c.w);
        }
    }
    const float rm0 = g_rmax[t0];
    const float rm1 = g_rmax[t1];
    const float r20 = rm0 * LOG2E;   // row shift in log2 domain
    const float r21 = rm1 * LOG2E;

    // Rp2 = (max_{t,k} trans + ln 64) * log2e  -- per-step growth bound const.
    const float maxT = funmap(__reduce_max_sync(0xFFFFFFFFu,
                              fmap(fmaxf(rm0, rm1))));
    const float Rp2 = (maxT + LN64) * LOG2E;

    const float* fptr = feats + (long)b * SS * TT;
    const float* mptr = masks + (long)b * SS;

    // alpha0 = feats[:, 0, :]  (log2 domain)
    float2 a00 = *(const float2*)(fptr + t0);
    float A0 = a00.x * LOG2E;
    float A1 = a00.y * LOG2E;

    // output latches: A_out = Flat + lg2(Slat); init encodes alpha0
    float Flat0 = A0, Flat1 = A1;
    float Slat0 = 1.0f, Slat1 = 1.0f;

    // distance-2 feats/mask prefetch (paired LDG.64)
    float2 fA = __ldg((const float2*)(fptr + TT + t0));
    float  mA = __ldg(mptr + 1);
    float2 fB = __ldg((const float2*)(fptr + 2 * TT + t0));
    float  mB = __ldg(mptr + 2);

    // s_1 = exact warp max of A_0 ; P = 2^(A_0 - s_1)
    float sC = funmap(__reduce_max_sync(0xFFFFFFFFu, fmap(fmaxf(A0, A1))));
    float P0 = ex2(A0 - sC);
    float P1 = ex2(A1 - sC);
    // REDUX over positive P: int compare == float compare for x >= 0
    int redP = __reduce_max_sync(0xFFFFFFFFu, __float_as_int(fmaxf(P0, P1)));

    // LAGGED growth term: cmax for step 1, from |feat_1| (fA)
    int cmaxCur;
    {
        int ab = __reduce_max_sync(0xFFFFFFFFu,
                   max(__float_as_int(fA.x) & 0x7FFFFFFF,
                       __float_as_int(fA.y) & 0x7FFFFFFF));
        float mfa = __int_as_float(ab);     // >= max feat_1 (abs bound)
        cmaxCur = max(0, __float2int_ru(fmaf(mfa, LOG2E, Rp2)));
    }

    int p = 0;
#pragma unroll 2
    for (int i = 1; i < SS; i++) {
        // ---- chain head: publish P pair (one STS.64) ---------------------
        float* vb = vbuf[wid][p];
        *(float2*)(vb + t0) = make_float2(P0, P1);
        asm volatile("" ::: "memory");   // compiler barrier: no LDS hoist

        // ---- off-chain: prefetch i+2 early (clamped, branch-free) --------
        int ip2 = i + 2; ip2 = (ip2 < SS) ? ip2 : (SS - 1);
        float2 fC = __ldg((const float2*)(fptr + ip2 * TT + t0));
        float  mC = __ldg(mptr + ip2);

        // ---- issue-early, consume-next-iter: |feat_{i+1}| bound REDUX ----
        int redFN = __reduce_max_sync(0xFFFFFFFFu,
                      max(__float_as_int(fB.x) & 0x7FFFFFFF,
                          __float_as_int(fB.y) & 0x7FFFFFFF));

        // ---- off-chain: INTEGER shift maintenance (all lat-4 ALU) --------
        // e+1 = (redP>>23) - 126 > log2(maxP) ; d = (e+1) + cmax
        int d = ((redP >> 23) - 126) + cmaxCur;
        float sN = sC + __int2float_rn(d);
        float H  = __int_as_float((127 - d) << 23);   // 2^(-d), exact
        float F0 = fmaf(fA.x, LOG2E, sC + r20);
        float F1 = fmaf(fA.y, LOG2E, sC + r21);
        float G0 = ex2(F0 - sN);
        float G1 = ex2(F1 - sN);

        // ---- critical chain: dot S = sum_k E'[t][k] * P[k] ---------------
        const ulonglong2* vv = (const ulonglong2*)vb;
        u64 Aa0 = pk2(0.f, 0.f), Aa1 = Aa0, Bb0 = Aa0, Bb1 = Aa0;
#pragma unroll
        for (int j = 0; j < 16; j++) {
            ulonglong2 q = vv[j];
            Aa0 = fma2(q.x, e0[2 * j],     Aa0);
            Aa1 = fma2(q.y, e0[2 * j + 1], Aa1);
            Bb0 = fma2(q.x, e1[2 * j],     Bb0);
            Bb1 = fma2(q.y, e1[2 * j + 1], Bb1);
        }
        float s0lo, s0hi, s1lo, s1hi;
        upk2(s0lo, s0hi, add2(Aa0, Aa1));
        upk2(s1lo, s1hi, add2(Bb0, Bb1));
        float S0 = s0lo + s0hi;
        float S1 = s1lo + s1hi;

        // ---- chain tail: next P (1 FMUL + select; no MUFU) ---------------
        bool msk = (mA != 0.0f);
        P0 = msk ? S0 * G0 : P0 * H;
        P1 = msk ? S1 * G1 : P1 * H;
        redP = __reduce_max_sync(0xFFFFFFFFu, __float_as_int(fmaxf(P0, P1)));

        // ---- off-chain: latch (F,S) on masked steps (output path) --------
        Flat0 = msk ? F0 : Flat0;
        Flat1 = msk ? F1 : Flat1;
        Slat0 = msk ? S0 : Slat0;
        Slat1 = msk ? S1 : Slat1;

        // ---- off-chain: cmax for next iter (F2I off the chain) -----------
        cmaxCur = max(0, __float2int_ru(fmaf(__int_as_float(redFN),
                                             LOG2E, Rp2)));

        // rotate shift + prefetch registers
        sC = sN;
        fA = fB; mA = mB;
        fB = fC; mB = mC;
        p ^= 1;
    }

    // A = Flat + lg2(Slat), back to natural log (2 MUFU total, post-loop)
    float2 o;
    o.x = (Flat0 + lg2(Slat0)) * LN2;
    o.y = (Flat1 + lg2(Slat1)) * LN2;
    *(float2*)(out + b * TT + t0) = o;
}

// ---------------------------------------------------------------------------
// launch
// ---------------------------------------------------------------------------
extern "C" void kernel_launch(void* const* d_in, const int* in_sizes, int n_in,
                              void* d_out, int out_size) {
    const float* feats = (const float*)d_in[0];  // [512, 1024, 64]
    const float* masks = (const float*)d_in[1];  // [512, 1024]
    const float* trans = (const float*)d_in[2];  // [64, 64]
    float* out = (float*)d_out;                  // [512, 64]

    crf_prep_kernel<<<TT, TT>>>(trans);
    crf_scan_kernel<<<CTAS, WARPS_PER_CTA * 32>>>(feats, masks, out);
}